// round 8
// baseline (speedup 1.0000x reference)
#include <cuda_runtime.h>
#include <cuda_bf16.h>
#include <stdint.h>
#include <math.h>

#define S_LEN 2048
#define DDIM  128
#define BM 128
#define BN 64
#define NT 256

// smem map: two 64KB bf16 buffers (KH|KL|VH|VL), QL, raw stages
#define KHo 0
#define KLo 16384
#define VHo 32768
#define VLo 49152
#define BUF(s) ((s) * 65536)
#define QL_O 131072
#define KST  163840
#define VST  196608
#define SMEM_BYTES 229376
#define QH_SCRATCH (BUF(1) + VHo)   // 32KB prologue scratch inside buf1.V

static __device__ __forceinline__ uint32_t smem_u32(const void* p) {
    uint32_t a;
    asm("{ .reg .u64 t; cvta.to.shared.u64 t, %1; cvt.u32.u64 %0, t; }" : "=r"(a) : "l"(p));
    return a;
}
static __device__ __forceinline__ void ldsm_x4(uint32_t r[4], uint32_t a) {
    asm volatile("ldmatrix.sync.aligned.m8n8.x4.shared.b16 {%0,%1,%2,%3}, [%4];"
                 : "=r"(r[0]), "=r"(r[1]), "=r"(r[2]), "=r"(r[3]) : "r"(a));
}
static __device__ __forceinline__ void ldsm_x4t(uint32_t r[4], uint32_t a) {
    asm volatile("ldmatrix.sync.aligned.m8n8.x4.trans.shared.b16 {%0,%1,%2,%3}, [%4];"
                 : "=r"(r[0]), "=r"(r[1]), "=r"(r[2]), "=r"(r[3]) : "r"(a));
}
static __device__ __forceinline__ void mma16816(float c[4], const uint32_t a[4], const uint32_t b[2]) {
    asm volatile("mma.sync.aligned.m16n8k16.row.col.f32.bf16.bf16.f32 "
                 "{%0,%1,%2,%3}, {%4,%5,%6,%7}, {%8,%9}, {%0,%1,%2,%3};"
                 : "+f"(c[0]), "+f"(c[1]), "+f"(c[2]), "+f"(c[3])
                 : "r"(a[0]), "r"(a[1]), "r"(a[2]), "r"(a[3]), "r"(b[0]), "r"(b[1]));
}
static __device__ __forceinline__ void cp16(uint32_t dst, const void* src) {
    asm volatile("cp.async.cg.shared.global [%0], [%1], 16;" :: "r"(dst), "l"(src));
}
static __device__ __forceinline__ void cp_commit() {
    asm volatile("cp.async.commit_group;" ::: "memory");
}
static __device__ __forceinline__ void cp_wait0() {
    asm volatile("cp.async.wait_group 0;" ::: "memory");
}
static __device__ __forceinline__ float ex2(float x) {
    float y;
    asm("ex2.approx.f32 %0, %1;" : "=f"(y) : "f"(x));
    return y;
}
static __device__ __forceinline__ void split2(float x, float y, uint32_t& h, uint32_t& l) {
    __nv_bfloat16 hx = __float2bfloat16_rn(x), hy = __float2bfloat16_rn(y);
    h = ((uint32_t)__bfloat16_as_ushort(hy) << 16) | __bfloat16_as_ushort(hx);
    __nv_bfloat16 lx = __float2bfloat16_rn(x - __bfloat162float(hx));
    __nv_bfloat16 ly = __float2bfloat16_rn(y - __bfloat162float(hy));
    l = ((uint32_t)__bfloat16_as_ushort(ly) << 16) | __bfloat16_as_ushort(lx);
}

// per-thread convert of chunk c (own staged data -> own bf16 slots)
#define CONV_K(c, dstc) { int i_ = tid + (c) * NT; int row_ = i_ >> 5, k4_ = i_ & 31;            \
    uint32_t off_ = (uint32_t)(row_ * 256 + ((k4_ * 8) ^ ((row_ & 7) << 4)));                    \
    float4 f_ = *(const float4*)(sm + KST + (size_t)i_ * 16);                                    \
    uint32_t h0_, l0_, h1_, l1_; split2(f_.x, f_.y, h0_, l0_); split2(f_.z, f_.w, h1_, l1_);     \
    *(uint2*)((dstc) + KHo + off_) = make_uint2(h0_, h1_);                                       \
    *(uint2*)((dstc) + KLo + off_) = make_uint2(l0_, l1_); }
#define CONV_V(c, dstc) { int i_ = tid + (c) * NT; int row_ = i_ >> 5, k4_ = i_ & 31;            \
    uint32_t off_ = (uint32_t)(row_ * 256 + ((k4_ * 8) ^ ((row_ & 7) << 4)));                    \
    float4 f_ = *(const float4*)(sm + VST + (size_t)i_ * 16);                                    \
    uint32_t h0_, l0_, h1_, l1_; split2(f_.x, f_.y, h0_, l0_); split2(f_.z, f_.w, h1_, l1_);     \
    *(uint2*)((dstc) + VHo + off_) = make_uint2(h0_, h1_);                                       \
    *(uint2*)((dstc) + VLo + off_) = make_uint2(l0_, l1_); }
#define STAGE(stoff, gptr) { _Pragma("unroll")                                                   \
    for (int j_ = 0; j_ < 8; j_++) { int i_ = tid + j_ * NT;                                     \
        cp16(sb + (stoff) + i_ * 16, (const void*)((gptr) + (size_t)i_ * 4)); } }

__global__ __launch_bounds__(NT, 1)
void attn_hmma(const float* __restrict__ Q, const float* __restrict__ K,
               const float* __restrict__ V, float* __restrict__ O) {
    extern __shared__ char sm[];
    const uint32_t sb = smem_u32(sm);
    const int tid  = threadIdx.x;
    const int lane = tid & 31;
    const int w    = tid >> 5;
    const int qt    = gridDim.x - 1 - blockIdx.x;   // heavy CTAs first
    const int b     = blockIdx.y;
    const int qbase = qt * BM;
    const int ntile = 2 * qt + 2;                   // always even
    const int m0    = w * 16;

    const float* Qg = Q + (size_t)b * S_LEN * DDIM;
    const float* Kg = K + (size_t)b * S_LEN * DDIM;
    const float* Vg = V + (size_t)b * S_LEN * DDIM;
    float*       Og = O + (size_t)b * S_LEN * DDIM;

    // lane decodes
    const int aR   = m0 + (lane & 15);
    const int aK   = (lane & 16) ? 16 : 0;
    const int aXor = (aR & 7) << 4;
    const int kRow = (lane & 7) + ((lane & 16) ? 8 : 0);   // K x4: 2 n-tiles
    const int kCol = (lane & 8) ? 16 : 0;
    const int kXor = (lane & 7) << 4;
    const int vRow = (lane & 7) + ((lane & 8) ? 8 : 0);    // V x4t: 2 n-tiles
    const int vCol = (lane & 16) ? 16 : 0;
    const int vXor = (lane & 7) << 4;

    // ---- prologue: stage K0/V0, process Q ----
    STAGE(KST, Kg);
    STAGE(VST, Vg);
    cp_commit();
    for (int i = tid; i < BM * 32; i += NT) {
        int row = i >> 5, k4 = i & 31;
        float4 q = ((const float4*)Qg)[(size_t)(qbase + row) * 32 + k4];
        uint32_t h0, l0, h1, l1;
        split2(q.x, q.y, h0, l0); split2(q.z, q.w, h1, l1);
        uint32_t off = (uint32_t)(row * 256 + ((k4 * 8) ^ ((row & 7) << 4)));
        *(uint2*)(sm + QH_SCRATCH + off) = make_uint2(h0, h1);
        *(uint2*)(sm + QL_O + off)       = make_uint2(l0, l1);
    }
    __syncthreads();
    uint32_t qh[8][4];
    #pragma unroll
    for (int kk = 0; kk < 8; kk++)
        ldsm_x4(qh[kk], sb + QH_SCRATCH + aR * 256 + ((kk * 32 + aK) ^ aXor));
    cp_wait0();
    __syncthreads();   // scratch reads done

    // convert tile 0 (own chunks)
    #pragma unroll
    for (int c = 0; c < 8; c++) { CONV_K(c, sm + BUF(0)); CONV_V(c, sm + BUF(0)); }
    if (ntile > 1) {   // stage + convert K1 -> buf1.K
        STAGE(KST, Kg + (size_t)BN * DDIM);
        cp_commit();
        cp_wait0();
        #pragma unroll
        for (int c = 0; c < 8; c++) CONV_K(c, sm + BUF(1));
    }
    __syncthreads();   // buf0 (and buf1.K) visible everywhere
    if (ntile > 2) STAGE(KST, Kg + (size_t)2 * BN * DDIM);
    if (ntile > 1) STAGE(VST, Vg + (size_t)BN * DDIM);
    cp_commit();

    float o[16][4];
    #pragma unroll
    for (int n = 0; n < 16; n++)
        #pragma unroll
        for (int i = 0; i < 4; i++) o[n][i] = 0.f;
    float csA[8][4], csB[8][4];
    float mr0 = -INFINITY, mr1 = -INFINITY, l0r = 0.f, l1r = 0.f;

    const int r0gl = qbase + m0 + (lane >> 2);
    const int r1gl = r0gl + 8;
    const int cb   = (lane & 3) * 2;
    const float SCALE2 = 0.0883883476483184405f * 1.4426950408889634f;

    // ---- QK(0) -> csA ----
    {
        #pragma unroll
        for (int n = 0; n < 8; n++)
            #pragma unroll
            for (int i = 0; i < 4; i++) csA[n][i] = 0.f;
        const uint32_t bufK = sb + BUF(0);
        #pragma unroll
        for (int kk = 0; kk < 8; kk++) {
            uint32_t qlf[4];
            ldsm_x4(qlf, sb + QL_O + aR * 256 + ((kk * 32 + aK) ^ aXor));
            #pragma unroll
            for (int np = 0; np < 4; np++) {
                uint32_t bh[4], bl[4];
                uint32_t ad = bufK + (uint32_t)((np * 16 + kRow) * 256) + (uint32_t)((kk * 32 + kCol) ^ kXor);
                ldsm_x4(bh, ad + KHo);
                ldsm_x4(bl, ad + KLo);
                mma16816(csA[2*np],   qh[kk], bh);     mma16816(csA[2*np],   qlf, bh);
                mma16816(csA[2*np],   qh[kk], bl);
                mma16816(csA[2*np+1], qh[kk], bh + 2); mma16816(csA[2*np+1], qlf, bh + 2);
                mma16816(csA[2*np+1], qh[kk], bl + 2);
            }
        }
    }

    auto body = [&](int t, float (&csO)[8][4], float (&csN)[8][4]) {
        const int kb = t * BN;
        const bool m1 = (t + 1 < ntile), m2 = (t + 2 < ntile), m3 = (t + 3 < ntile);
        char* smA = sm + BUF(t & 1);
        char* smB = sm + BUF((t + 1) & 1);
        const uint32_t bufA = sb + (uint32_t)BUF(t & 1);
        const uint32_t bufB = sb + (uint32_t)BUF((t + 1) & 1);

        __syncthreads();   // all prior-phase smem reads/writes settled
        cp_wait0();        // staged raw tiles present

        // --- softmax part A on csO (S(t), issued last iter) ---
        float mx0 = -INFINITY, mx1 = -INFINITY;
        if (kb + BN - 1 > qbase + m0) {
            #pragma unroll
            for (int n = 0; n < 8; n++) {
                int jg = kb + n * 8 + cb;
                float x0 = csO[n][0] * SCALE2; if (jg > r0gl)     x0 = -1e9f;
                float x1 = csO[n][1] * SCALE2; if (jg + 1 > r0gl) x1 = -1e9f;
                float x2 = csO[n][2] * SCALE2; if (jg > r1gl)     x2 = -1e9f;
                float x3 = csO[n][3] * SCALE2; if (jg + 1 > r1gl) x3 = -1e9f;
                csO[n][0] = x0; csO[n][1] = x1; csO[n][2] = x2; csO[n][3] = x3;
                mx0 = fmaxf(mx0, fmaxf(x0, x1));
                mx1 = fmaxf(mx1, fmaxf(x2, x3));
            }
        } else {
            #pragma unroll
            for (int n = 0; n < 8; n++) {
                float x0 = csO[n][0] * SCALE2, x1 = csO[n][1] * SCALE2;
                float x2 = csO[n][2] * SCALE2, x3 = csO[n][3] * SCALE2;
                csO[n][0] = x0; csO[n][1] = x1; csO[n][2] = x2; csO[n][3] = x3;
                mx0 = fmaxf(mx0, fmaxf(x0, x1));
                mx1 = fmaxf(mx1, fmaxf(x2, x3));
            }
        }
        mx0 = fmaxf(mx0, __shfl_xor_sync(0xffffffffu, mx0, 1));
        mx0 = fmaxf(mx0, __shfl_xor_sync(0xffffffffu, mx0, 2));
        mx1 = fmaxf(mx1, __shfl_xor_sync(0xffffffffu, mx1, 1));
        mx1 = fmaxf(mx1, __shfl_xor_sync(0xffffffffu, mx1, 2));
        float mn0 = fmaxf(mr0, mx0), mn1 = fmaxf(mr1, mx1);
        float al0 = ex2(mr0 - mn0), al1 = ex2(mr1 - mn1);
        mr0 = mn0; mr1 = mn1;

        // --- QK(t+1) -> csN (independent of softmax; fills tensor pipe) ---
        if (m1) {
            #pragma unroll
            for (int n = 0; n < 8; n++)
                #pragma unroll
                for (int i = 0; i < 4; i++) csN[n][i] = 0.f;
            #pragma unroll
            for (int kk = 0; kk < 8; kk++) {
                if (m2) CONV_K(kk, smA);   // K(t+2) -> dead K slot
                uint32_t qlf[4];
                ldsm_x4(qlf, sb + QL_O + aR * 256 + ((kk * 32 + aK) ^ aXor));
                #pragma unroll
                for (int np = 0; np < 4; np++) {
                    uint32_t bh[4], bl[4];
                    uint32_t ad = bufB + (uint32_t)((np * 16 + kRow) * 256) + (uint32_t)((kk * 32 + kCol) ^ kXor);
                    ldsm_x4(bh, ad + KHo);
                    ldsm_x4(bl, ad + KLo);
                    mma16816(csN[2*np],   qh[kk], bh);     mma16816(csN[2*np],   qlf, bh);
                    mma16816(csN[2*np],   qh[kk], bl);
                    mma16816(csN[2*np+1], qh[kk], bh + 2); mma16816(csN[2*np+1], qlf, bh + 2);
                    mma16816(csN[2*np+1], qh[kk], bl + 2);
                }
            }
        }

        // --- rescale o, exps in place (overlaps in-flight QK MMAs) ---
        #pragma unroll
        for (int n = 0; n < 16; n++) {
            o[n][0] *= al0; o[n][1] *= al0;
            o[n][2] *= al1; o[n][3] *= al1;
        }
        float s0 = 0.f, s1 = 0.f;
        #pragma unroll
        for (int n = 0; n < 8; n++) {
            float p0 = ex2(csO[n][0] - mn0);
            float p1 = ex2(csO[n][1] - mn0);
            float p2 = ex2(csO[n][2] - mn1);
            float p3 = ex2(csO[n][3] - mn1);
            csO[n][0] = p0; csO[n][1] = p1; csO[n][2] = p2; csO[n][3] = p3;
            s0 += p0 + p1; s1 += p2 + p3;
        }

        // --- PV(t) -> o ---
        #pragma unroll
        for (int g = 0; g < 4; g++) {
            if (m1) { CONV_V(g * 2, smB); CONV_V(g * 2 + 1, smB); }   // V(t+1) -> dead V slot
            uint32_t ph[4], pl[4];
            split2(csO[2*g][0],   csO[2*g][1],   ph[0], pl[0]);
            split2(csO[2*g][2],   csO[2*g][3],   ph[1], pl[1]);
            split2(csO[2*g+1][0], csO[2*g+1][1], ph[2], pl[2]);
            split2(csO[2*g+1][2], csO[2*g+1][3], ph[3], pl[3]);
            #pragma unroll
            for (int np = 0; np < 8; np++) {
                uint32_t bh[4], bl[4];
                uint32_t ad = bufA + (uint32_t)((g * 16 + vRow) * 256) + (uint32_t)((np * 32 + vCol) ^ vXor);
                ldsm_x4t(bh, ad + VHo);
                ldsm_x4t(bl, ad + VLo);
                mma16816(o[2*np],   ph, bh);     mma16816(o[2*np],   pl, bh);
                mma16816(o[2*np],   ph, bl);
                mma16816(o[2*np+1], ph, bh + 2); mma16816(o[2*np+1], pl, bh + 2);
                mma16816(o[2*np+1], ph, bl + 2);
            }
        }
        s0 += __shfl_xor_sync(0xffffffffu, s0, 1);
        s0 += __shfl_xor_sync(0xffffffffu, s0, 2);
        s1 += __shfl_xor_sync(0xffffffffu, s1, 1);
        s1 += __shfl_xor_sync(0xffffffffu, s1, 2);
        l0r = l0r * al0 + s0;
        l1r = l1r * al1 + s1;

        // --- restage raw tiles for next iteration's converts ---
        if (m3) STAGE(KST, Kg + (size_t)(kb + 3 * BN) * DDIM);
        if (m2) STAGE(VST, Vg + (size_t)(kb + 2 * BN) * DDIM);
        if (m2) cp_commit();
    };

    for (int t = 0; t < ntile; t += 2) {
        body(t,     csA, csB);
        body(t + 1, csB, csA);
    }

    // ---- epilogue ----
    const float inv0 = 1.f / l0r, inv1 = 1.f / l1r;
    #pragma unroll
    for (int n = 0; n < 16; n++) {
        int col = n * 8 + cb;
        *(float2*)(Og + (size_t)r0gl * DDIM + col) = make_float2(o[n][0] * inv0, o[n][1] * inv0);
        *(float2*)(Og + (size_t)r1gl * DDIM + col) = make_float2(o[n][2] * inv1, o[n][3] * inv1);
    }
}

extern "C" void kernel_launch(void* const* d_in, const int* in_sizes, int n_in,
                              void* d_out, int out_size) {
    const float* Q = (const float*)d_in[0];
    const float* K = (const float*)d_in[1];
    const float* V = (const float*)d_in[2];
    float*       O = (float*)d_out;
    int B = in_sizes[0] / (S_LEN * DDIM);
    cudaFuncSetAttribute(attn_hmma, cudaFuncAttributeMaxDynamicSharedMemorySize, SMEM_BYTES);
    dim3 grid(S_LEN / BM, B);
    attn_hmma<<<grid, NT, SMEM_BYTES>>>(Q, K, V, O);
}

// round 9
// speedup vs baseline: 1.6134x; 1.6134x over previous
#include <cuda_runtime.h>
#include <cuda_fp16.h>
#include <stdint.h>
#include <math.h>

#define S_LEN 2048
#define DDIM  128
#define BM 128
#define BN 64
#define NT 256

// smem: two 32KB fp16 buffers (KH|VH), raw fp32 stages
#define KHo 0
#define VHo 16384
#define BUF(s) ((s) * 32768)
#define KST 65536
#define VST 98304
#define SMEM_BYTES 131072
// prologue Q scratch overlays both buffers
#define QH_S 0
#define QL_S 32768

static __device__ __forceinline__ uint32_t smem_u32(const void* p) {
    uint32_t a;
    asm("{ .reg .u64 t; cvta.to.shared.u64 t, %1; cvt.u32.u64 %0, t; }" : "=r"(a) : "l"(p));
    return a;
}
static __device__ __forceinline__ void ldsm_x4(uint32_t r[4], uint32_t a) {
    asm volatile("ldmatrix.sync.aligned.m8n8.x4.shared.b16 {%0,%1,%2,%3}, [%4];"
                 : "=r"(r[0]), "=r"(r[1]), "=r"(r[2]), "=r"(r[3]) : "r"(a));
}
static __device__ __forceinline__ void ldsm_x4t(uint32_t r[4], uint32_t a) {
    asm volatile("ldmatrix.sync.aligned.m8n8.x4.trans.shared.b16 {%0,%1,%2,%3}, [%4];"
                 : "=r"(r[0]), "=r"(r[1]), "=r"(r[2]), "=r"(r[3]) : "r"(a));
}
static __device__ __forceinline__ void mma16816(float c[4], const uint32_t a[4], const uint32_t b[2]) {
    asm volatile("mma.sync.aligned.m16n8k16.row.col.f32.f16.f16.f32 "
                 "{%0,%1,%2,%3}, {%4,%5,%6,%7}, {%8,%9}, {%0,%1,%2,%3};"
                 : "+f"(c[0]), "+f"(c[1]), "+f"(c[2]), "+f"(c[3])
                 : "r"(a[0]), "r"(a[1]), "r"(a[2]), "r"(a[3]), "r"(b[0]), "r"(b[1]));
}
static __device__ __forceinline__ void cp16(uint32_t dst, const void* src) {
    asm volatile("cp.async.cg.shared.global [%0], [%1], 16;" :: "r"(dst), "l"(src));
}
static __device__ __forceinline__ void cp_commit() {
    asm volatile("cp.async.commit_group;" ::: "memory");
}
static __device__ __forceinline__ void cp_wait0() {
    asm volatile("cp.async.wait_group 0;" ::: "memory");
}
static __device__ __forceinline__ float ex2(float x) {
    float y;
    asm("ex2.approx.f32 %0, %1;" : "=f"(y) : "f"(x));
    return y;
}
static __device__ __forceinline__ uint32_t packh2(float x, float y) {
    __half2 h = __floats2half2_rn(x, y);
    return *reinterpret_cast<uint32_t*>(&h);
}
static __device__ __forceinline__ void split2h(float x, float y, uint32_t& h, uint32_t& l) {
    __half hx = __float2half_rn(x), hy = __float2half_rn(y);
    h = ((uint32_t)__half_as_ushort(hy) << 16) | __half_as_ushort(hx);
    __half lx = __float2half_rn(x - __half2float(hx));
    __half ly = __float2half_rn(y - __half2float(hy));
    l = ((uint32_t)__half_as_ushort(ly) << 16) | __half_as_ushort(lx);
}

// per-thread convert of chunk c: raw fp32 stage -> fp16 H tile (own data only)
#define CONV_K(c, dstc) { int i_ = tid + (c) * NT; int row_ = i_ >> 5, k4_ = i_ & 31;          \
    uint32_t off_ = (uint32_t)(row_ * 256 + ((k4_ * 8) ^ ((row_ & 7) << 4)));                  \
    float4 f_ = *(const float4*)(sm + KST + (size_t)i_ * 16);                                  \
    *(uint2*)((dstc) + KHo + off_) = make_uint2(packh2(f_.x, f_.y), packh2(f_.z, f_.w)); }
#define CONV_V(c, dstc) { int i_ = tid + (c) * NT; int row_ = i_ >> 5, k4_ = i_ & 31;          \
    uint32_t off_ = (uint32_t)(row_ * 256 + ((k4_ * 8) ^ ((row_ & 7) << 4)));                  \
    float4 f_ = *(const float4*)(sm + VST + (size_t)i_ * 16);                                  \
    *(uint2*)((dstc) + VHo + off_) = make_uint2(packh2(f_.x, f_.y), packh2(f_.z, f_.w)); }
#define STAGE(stoff, gptr) { _Pragma("unroll")                                                 \
    for (int j_ = 0; j_ < 8; j_++) { int i_ = tid + j_ * NT;                                   \
        cp16(sb + (stoff) + i_ * 16, (const void*)((gptr) + (size_t)i_ * 4)); } }

__global__ __launch_bounds__(NT, 1)
void attn_hmma(const float* __restrict__ Q, const float* __restrict__ K,
               const float* __restrict__ V, float* __restrict__ O) {
    extern __shared__ char sm[];
    const uint32_t sb = smem_u32(sm);
    const int tid  = threadIdx.x;
    const int lane = tid & 31;
    const int w    = tid >> 5;
    const int qt    = gridDim.x - 1 - blockIdx.x;   // heavy CTAs first
    const int b     = blockIdx.y;
    const int qbase = qt * BM;
    const int ntile = 2 * qt + 2;
    const int m0    = w * 16;

    const float* Qg = Q + (size_t)b * S_LEN * DDIM;
    const float* Kg = K + (size_t)b * S_LEN * DDIM;
    const float* Vg = V + (size_t)b * S_LEN * DDIM;
    float*       Og = O + (size_t)b * S_LEN * DDIM;

    // lane decodes (verified in R8 run)
    const int aR   = m0 + (lane & 15);
    const int aK   = (lane & 16) ? 16 : 0;
    const int aXor = (aR & 7) << 4;
    const int kRow = (lane & 7) + ((lane & 16) ? 8 : 0);   // K x4: 2 n-tiles
    const int kCol = (lane & 8) ? 16 : 0;
    const int kXor = (lane & 7) << 4;
    const int vRow = (lane & 7) + ((lane & 8) ? 8 : 0);    // V x4t: 2 n-tiles
    const int vCol = (lane & 16) ? 16 : 0;
    const int vXor = (lane & 7) << 4;

    // ---- prologue ----
    STAGE(KST, Kg);
    STAGE(VST, Vg);
    cp_commit();
    for (int i = tid; i < BM * 32; i += NT) {
        int row = i >> 5, k4 = i & 31;
        float4 q = ((const float4*)Qg)[(size_t)(qbase + row) * 32 + k4];
        uint32_t h0, l0, h1, l1;
        split2h(q.x, q.y, h0, l0); split2h(q.z, q.w, h1, l1);
        uint32_t off = (uint32_t)(row * 256 + ((k4 * 8) ^ ((row & 7) << 4)));
        *(uint2*)(sm + QH_S + off) = make_uint2(h0, h1);
        *(uint2*)(sm + QL_S + off) = make_uint2(l0, l1);
    }
    __syncthreads();
    uint32_t qh[8][4], ql[8][4];
    #pragma unroll
    for (int kk = 0; kk < 8; kk++) {
        ldsm_x4(qh[kk], sb + QH_S + aR * 256 + ((kk * 32 + aK) ^ aXor));
        ldsm_x4(ql[kk], sb + QL_S + aR * 256 + ((kk * 32 + aK) ^ aXor));
    }
    cp_wait0();
    __syncthreads();   // Q scratch reads done; buffers may be written
    #pragma unroll
    for (int c = 0; c < 8; c++) { CONV_K(c, sm + BUF(0)); CONV_V(c, sm + BUF(0)); }
    __syncthreads();   // buf0 visible
    if (ntile > 1) {
        STAGE(KST, Kg + (size_t)BN * DDIM);
        STAGE(VST, Vg + (size_t)BN * DDIM);
        cp_commit();
    }

    float o[16][4];
    #pragma unroll
    for (int n = 0; n < 16; n++)
        #pragma unroll
        for (int i = 0; i < 4; i++) o[n][i] = 0.f;
    float mr0 = -INFINITY, mr1 = -INFINITY, l0r = 0.f, l1r = 0.f;

    const int r0gl = qbase + m0 + (lane >> 2);
    const int r1gl = r0gl + 8;
    const int cb   = (lane & 3) * 2;
    const float SCALE2 = 0.0883883476483184405f * 1.4426950408889634f;   // 1/sqrt(128)*log2(e)

    for (int t = 0; t < ntile; t++) {
        const int kb = t * BN;
        const bool more = (t + 1 < ntile);
        char* smB = sm + BUF((t + 1) & 1);
        const uint32_t bufA = sb + (uint32_t)BUF(t & 1);

        if (more) cp_wait0();   // own raw chunks of tile t+1 staged
        __syncthreads();        // everyone done reading bufB (tile t-1)

        // ---- S = Q K^T (hQ + lQ) · hK, convert t+1 interleaved ----
        float cs[8][4];
        #pragma unroll
        for (int n = 0; n < 8; n++)
            #pragma unroll
            for (int i = 0; i < 4; i++) cs[n][i] = 0.f;

        #pragma unroll
        for (int kk = 0; kk < 8; kk++) {
            if (more) { CONV_K(kk, smB); CONV_V(kk, smB); }
            #pragma unroll
            for (int np = 0; np < 4; np++) {
                uint32_t bh[4];
                ldsm_x4(bh, bufA + KHo + (uint32_t)((np * 16 + kRow) * 256) + (uint32_t)((kk * 32 + kCol) ^ kXor));
                mma16816(cs[2*np],   qh[kk], bh);
                mma16816(cs[2*np],   ql[kk], bh);
                mma16816(cs[2*np+1], qh[kk], bh + 2);
                mma16816(cs[2*np+1], ql[kk], bh + 2);
            }
        }

        __syncthreads();   // convert reads of staging drained
        if (t + 2 < ntile) {
            STAGE(KST, Kg + (size_t)(kb + 2 * BN) * DDIM);
            STAGE(VST, Vg + (size_t)(kb + 2 * BN) * DDIM);
            cp_commit();
        }

        // ---- softmax (log2 domain) ----
        float mx0 = -INFINITY, mx1 = -INFINITY;
        if (kb + BN - 1 > qbase + m0) {
            #pragma unroll
            for (int n = 0; n < 8; n++) {
                int jg = kb + n * 8 + cb;
                float x0 = cs[n][0] * SCALE2; if (jg > r0gl)     x0 = -1e9f;
                float x1 = cs[n][1] * SCALE2; if (jg + 1 > r0gl) x1 = -1e9f;
                float x2 = cs[n][2] * SCALE2; if (jg > r1gl)     x2 = -1e9f;
                float x3 = cs[n][3] * SCALE2; if (jg + 1 > r1gl) x3 = -1e9f;
                cs[n][0] = x0; cs[n][1] = x1; cs[n][2] = x2; cs[n][3] = x3;
                mx0 = fmaxf(mx0, fmaxf(x0, x1));
                mx1 = fmaxf(mx1, fmaxf(x2, x3));
            }
        } else {
            #pragma unroll
            for (int n = 0; n < 8; n++) {
                float x0 = cs[n][0] * SCALE2, x1 = cs[n][1] * SCALE2;
                float x2 = cs[n][2] * SCALE2, x3 = cs[n][3] * SCALE2;
                cs[n][0] = x0; cs[n][1] = x1; cs[n][2] = x2; cs[n][3] = x3;
                mx0 = fmaxf(mx0, fmaxf(x0, x1));
                mx1 = fmaxf(mx1, fmaxf(x2, x3));
            }
        }
        mx0 = fmaxf(mx0, __shfl_xor_sync(0xffffffffu, mx0, 1));
        mx0 = fmaxf(mx0, __shfl_xor_sync(0xffffffffu, mx0, 2));
        mx1 = fmaxf(mx1, __shfl_xor_sync(0xffffffffu, mx1, 1));
        mx1 = fmaxf(mx1, __shfl_xor_sync(0xffffffffu, mx1, 2));
        float mn0 = fmaxf(mr0, mx0), mn1 = fmaxf(mr1, mx1);
        float al0 = ex2(mr0 - mn0), al1 = ex2(mr1 - mn1);
        mr0 = mn0; mr1 = mn1;

        #pragma unroll
        for (int n = 0; n < 16; n++) {
            o[n][0] *= al0; o[n][1] *= al0;
            o[n][2] *= al1; o[n][3] *= al1;
        }

        // ---- PV (hP + lP) · hV, exp fused per k-group ----
        float s0 = 0.f, s1 = 0.f;
        #pragma unroll
        for (int g = 0; g < 4; g++) {
            float p00 = ex2(cs[2*g][0]   - mn0), p01 = ex2(cs[2*g][1]   - mn0);
            float p02 = ex2(cs[2*g][2]   - mn1), p03 = ex2(cs[2*g][3]   - mn1);
            float p10 = ex2(cs[2*g+1][0] - mn0), p11 = ex2(cs[2*g+1][1] - mn0);
            float p12 = ex2(cs[2*g+1][2] - mn1), p13 = ex2(cs[2*g+1][3] - mn1);
            s0 += p00 + p01 + p10 + p11;
            s1 += p02 + p03 + p12 + p13;
            uint32_t ph[4], pl[4];
            split2h(p00, p01, ph[0], pl[0]);
            split2h(p02, p03, ph[1], pl[1]);
            split2h(p10, p11, ph[2], pl[2]);
            split2h(p12, p13, ph[3], pl[3]);
            #pragma unroll
            for (int np = 0; np < 8; np++) {
                uint32_t bh[4];
                ldsm_x4t(bh, bufA + VHo + (uint32_t)((g * 16 + vRow) * 256) + (uint32_t)((np * 32 + vCol) ^ vXor));
                mma16816(o[2*np],   ph, bh);
                mma16816(o[2*np],   pl, bh);
                mma16816(o[2*np+1], ph, bh + 2);
                mma16816(o[2*np+1], pl, bh + 2);
            }
        }
        s0 += __shfl_xor_sync(0xffffffffu, s0, 1);
        s0 += __shfl_xor_sync(0xffffffffu, s0, 2);
        s1 += __shfl_xor_sync(0xffffffffu, s1, 1);
        s1 += __shfl_xor_sync(0xffffffffu, s1, 2);
        l0r = l0r * al0 + s0;
        l1r = l1r * al1 + s1;
    }

    // ---- epilogue ----
    const float inv0 = 1.f / l0r, inv1 = 1.f / l1r;
    #pragma unroll
    for (int n = 0; n < 16; n++) {
        int col = n * 8 + cb;
        *(float2*)(Og + (size_t)r0gl * DDIM + col) = make_float2(o[n][0] * inv0, o[n][1] * inv0);
        *(float2*)(Og + (size_t)r1gl * DDIM + col) = make_float2(o[n][2] * inv1, o[n][3] * inv1);
    }
}

extern "C" void kernel_launch(void* const* d_in, const int* in_sizes, int n_in,
                              void* d_out, int out_size) {
    const float* Q = (const float*)d_in[0];
    const float* K = (const float*)d_in[1];
    const float* V = (const float*)d_in[2];
    float*       O = (float*)d_out;
    int B = in_sizes[0] / (S_LEN * DDIM);
    cudaFuncSetAttribute(attn_hmma, cudaFuncAttributeMaxDynamicSharedMemorySize, SMEM_BYTES);
    dim3 grid(S_LEN / BM, B);
    attn_hmma<<<grid, NT, SMEM_BYTES>>>(Q, K, V, O);
}

// round 10
// speedup vs baseline: 1.6412x; 1.0172x over previous
#include <cuda_runtime.h>
#include <cuda_fp16.h>
#include <stdint.h>
#include <math.h>

#define S_LEN 2048
#define DDIM  128
#define BM 128
#define BN 64
#define NT 256

// smem: two 32KB fp16 buffers (KH|VH), raw fp32 stages
#define KHo 0
#define VHo 16384
#define BUF(s) ((s) * 32768)
#define KST 65536
#define VST 98304
#define SMEM_BYTES 131072
// prologue Q scratch overlays both buffers
#define QH_S 0
#define QL_S 32768

static __device__ __forceinline__ uint32_t smem_u32(const void* p) {
    uint32_t a;
    asm("{ .reg .u64 t; cvta.to.shared.u64 t, %1; cvt.u32.u64 %0, t; }" : "=r"(a) : "l"(p));
    return a;
}
static __device__ __forceinline__ void ldsm_x4(uint32_t r[4], uint32_t a) {
    asm volatile("ldmatrix.sync.aligned.m8n8.x4.shared.b16 {%0,%1,%2,%3}, [%4];"
                 : "=r"(r[0]), "=r"(r[1]), "=r"(r[2]), "=r"(r[3]) : "r"(a));
}
static __device__ __forceinline__ void ldsm_x4t(uint32_t r[4], uint32_t a) {
    asm volatile("ldmatrix.sync.aligned.m8n8.x4.trans.shared.b16 {%0,%1,%2,%3}, [%4];"
                 : "=r"(r[0]), "=r"(r[1]), "=r"(r[2]), "=r"(r[3]) : "r"(a));
}
static __device__ __forceinline__ void mma16816(float c[4], const uint32_t a[4], const uint32_t b[2]) {
    asm volatile("mma.sync.aligned.m16n8k16.row.col.f32.f16.f16.f32 "
                 "{%0,%1,%2,%3}, {%4,%5,%6,%7}, {%8,%9}, {%0,%1,%2,%3};"
                 : "+f"(c[0]), "+f"(c[1]), "+f"(c[2]), "+f"(c[3])
                 : "r"(a[0]), "r"(a[1]), "r"(a[2]), "r"(a[3]), "r"(b[0]), "r"(b[1]));
}
static __device__ __forceinline__ void cp16(uint32_t dst, const void* src) {
    asm volatile("cp.async.cg.shared.global [%0], [%1], 16;" :: "r"(dst), "l"(src));
}
static __device__ __forceinline__ void cp_commit() {
    asm volatile("cp.async.commit_group;" ::: "memory");
}
static __device__ __forceinline__ void cp_wait0() {
    asm volatile("cp.async.wait_group 0;" ::: "memory");
}
static __device__ __forceinline__ float ex2(float x) {
    float y;
    asm("ex2.approx.f32 %0, %1;" : "=f"(y) : "f"(x));
    return y;
}
static __device__ __forceinline__ uint32_t packh2(float x, float y) {
    __half2 h = __floats2half2_rn(x, y);
    return *reinterpret_cast<uint32_t*>(&h);
}
static __device__ __forceinline__ void split2h(float x, float y, uint32_t& h, uint32_t& l) {
    __half hx = __float2half_rn(x), hy = __float2half_rn(y);
    h = ((uint32_t)__half_as_ushort(hy) << 16) | __half_as_ushort(hx);
    __half lx = __float2half_rn(x - __half2float(hx));
    __half ly = __float2half_rn(y - __half2float(hy));
    l = ((uint32_t)__half_as_ushort(ly) << 16) | __half_as_ushort(lx);
}

#define CONV_K(c, dstc) { int i_ = tid + (c) * NT; int row_ = i_ >> 5, k4_ = i_ & 31;          \
    uint32_t off_ = (uint32_t)(row_ * 256 + ((k4_ * 8) ^ ((row_ & 7) << 4)));                  \
    float4 f_ = *(const float4*)(sm + KST + (size_t)i_ * 16);                                  \
    *(uint2*)((dstc) + KHo + off_) = make_uint2(packh2(f_.x, f_.y), packh2(f_.z, f_.w)); }
#define CONV_V(c, dstc) { int i_ = tid + (c) * NT; int row_ = i_ >> 5, k4_ = i_ & 31;          \
    uint32_t off_ = (uint32_t)(row_ * 256 + ((k4_ * 8) ^ ((row_ & 7) << 4)));                  \
    float4 f_ = *(const float4*)(sm + VST + (size_t)i_ * 16);                                  \
    *(uint2*)((dstc) + VHo + off_) = make_uint2(packh2(f_.x, f_.y), packh2(f_.z, f_.w)); }
#define STAGE(stoff, gptr) { _Pragma("unroll")                                                 \
    for (int j_ = 0; j_ < 8; j_++) { int i_ = tid + j_ * NT;                                   \
        cp16(sb + (stoff) + i_ * 16, (const void*)((gptr) + (size_t)i_ * 4)); } }

__global__ __launch_bounds__(NT, 1)
void attn_hmma(const float* __restrict__ Q, const float* __restrict__ K,
               const float* __restrict__ V, float* __restrict__ O) {
    extern __shared__ char sm[];
    const uint32_t sb = smem_u32(sm);
    const int tid  = threadIdx.x;
    const int lane = tid & 31;
    const int w    = tid >> 5;
    const int qt    = gridDim.x - 1 - blockIdx.x;   // heavy CTAs first
    const int b     = blockIdx.y;
    const int qbase = qt * BM;
    const int ntile = 2 * qt + 2;
    const int m0    = w * 16;

    const float* Qg = Q + (size_t)b * S_LEN * DDIM;
    const float* Kg = K + (size_t)b * S_LEN * DDIM;
    const float* Vg = V + (size_t)b * S_LEN * DDIM;
    float*       Og = O + (size_t)b * S_LEN * DDIM;

    // lane decodes
    const int aR   = m0 + (lane & 15);
    const int aK   = (lane & 16) ? 16 : 0;
    const int aXor = (aR & 7) << 4;
    const int kRow = (lane & 7) + ((lane & 16) ? 8 : 0);   // K x4: 2 n-tiles
    const int kCol = (lane & 8) ? 16 : 0;
    const int kXor = (lane & 7) << 4;
    const int vRow = (lane & 7) + ((lane & 8) ? 8 : 0);    // V x4t: 2 n-tiles
    const int vCol = (lane & 16) ? 16 : 0;
    const int vXor = (lane & 7) << 4;

    // ---- prologue ----
    STAGE(KST, Kg);
    STAGE(VST, Vg);
    cp_commit();
    for (int i = tid; i < BM * 32; i += NT) {
        int row = i >> 5, k4 = i & 31;
        float4 q = ((const float4*)Qg)[(size_t)(qbase + row) * 32 + k4];
        uint32_t h0, l0, h1, l1;
        split2h(q.x, q.y, h0, l0); split2h(q.z, q.w, h1, l1);
        uint32_t off = (uint32_t)(row * 256 + ((k4 * 8) ^ ((row & 7) << 4)));
        *(uint2*)(sm + QH_S + off) = make_uint2(h0, h1);
        *(uint2*)(sm + QL_S + off) = make_uint2(l0, l1);
    }
    __syncthreads();
    uint32_t qh[8][4], ql[8][4];
    #pragma unroll
    for (int kk = 0; kk < 8; kk++) {
        ldsm_x4(qh[kk], sb + QH_S + aR * 256 + ((kk * 32 + aK) ^ aXor));
        ldsm_x4(ql[kk], sb + QL_S + aR * 256 + ((kk * 32 + aK) ^ aXor));
    }
    cp_wait0();
    __syncthreads();   // Q scratch reads done; buffers may be written
    #pragma unroll
    for (int c = 0; c < 8; c++) { CONV_K(c, sm + BUF(0)); CONV_V(c, sm + BUF(0)); }
    __syncthreads();   // buf0 visible
    if (ntile > 1) {
        STAGE(KST, Kg + (size_t)BN * DDIM);
        STAGE(VST, Vg + (size_t)BN * DDIM);
        cp_commit();
    }

    float o[16][4];
    #pragma unroll
    for (int n = 0; n < 16; n++)
        #pragma unroll
        for (int i = 0; i < 4; i++) o[n][i] = 0.f;
    float mr0 = -INFINITY, mr1 = -INFINITY, l0r = 0.f, l1r = 0.f;

    const int r0gl = qbase + m0 + (lane >> 2);
    const int r1gl = r0gl + 8;
    const int cb   = (lane & 3) * 2;
    const float SCALE2 = 0.0883883476483184405f * 1.4426950408889634f;   // 1/sqrt(128)*log2(e)

    for (int t = 0; t < ntile; t++) {
        const int kb = t * BN;
        const bool more = (t + 1 < ntile);
        char* smB = sm + BUF((t + 1) & 1);
        const uint32_t bufA = sb + (uint32_t)BUF(t & 1);

        if (more) cp_wait0();   // own raw chunks of tile t+1 staged
        __syncthreads();        // everyone done reading bufB (tile t-1)

        // ---- S = Q K^T, two sweeps (qh then ql) to break accumulator RAW chains ----
        float cs[8][4];
        #pragma unroll
        for (int n = 0; n < 8; n++)
            #pragma unroll
            for (int i = 0; i < 4; i++) cs[n][i] = 0.f;

        #pragma unroll
        for (int kk = 0; kk < 8; kk++) {
            if (more) { CONV_K(kk, smB); CONV_V(kk, smB); }
            // sweep 1: qh x all np  (8 independent accumulators in flight)
            #pragma unroll
            for (int np = 0; np < 4; np++) {
                uint32_t bh[4];
                ldsm_x4(bh, bufA + KHo + (uint32_t)((np * 16 + kRow) * 256) + (uint32_t)((kk * 32 + kCol) ^ kXor));
                mma16816(cs[2*np],   qh[kk], bh);
                mma16816(cs[2*np+1], qh[kk], bh + 2);
            }
            // sweep 2: ql x all np  (re-ldsm; reuse distance >= 8 MMAs)
            #pragma unroll
            for (int np = 0; np < 4; np++) {
                uint32_t bh[4];
                ldsm_x4(bh, bufA + KHo + (uint32_t)((np * 16 + kRow) * 256) + (uint32_t)((kk * 32 + kCol) ^ kXor));
                mma16816(cs[2*np],   ql[kk], bh);
                mma16816(cs[2*np+1], ql[kk], bh + 2);
            }
        }

        __syncthreads();   // convert reads of staging drained
        if (t + 2 < ntile) {
            STAGE(KST, Kg + (size_t)(kb + 2 * BN) * DDIM);
            STAGE(VST, Vg + (size_t)(kb + 2 * BN) * DDIM);
            cp_commit();
        }

        // ---- softmax (log2 domain) ----
        float mx0 = -INFINITY, mx1 = -INFINITY;
        if (kb + BN - 1 > qbase + m0) {
            #pragma unroll
            for (int n = 0; n < 8; n++) {
                int jg = kb + n * 8 + cb;
                float x0 = cs[n][0] * SCALE2; if (jg > r0gl)     x0 = -1e9f;
                float x1 = cs[n][1] * SCALE2; if (jg + 1 > r0gl) x1 = -1e9f;
                float x2 = cs[n][2] * SCALE2; if (jg > r1gl)     x2 = -1e9f;
                float x3 = cs[n][3] * SCALE2; if (jg + 1 > r1gl) x3 = -1e9f;
                cs[n][0] = x0; cs[n][1] = x1; cs[n][2] = x2; cs[n][3] = x3;
                mx0 = fmaxf(mx0, fmaxf(x0, x1));
                mx1 = fmaxf(mx1, fmaxf(x2, x3));
            }
        } else {
            #pragma unroll
            for (int n = 0; n < 8; n++) {
                float x0 = cs[n][0] * SCALE2, x1 = cs[n][1] * SCALE2;
                float x2 = cs[n][2] * SCALE2, x3 = cs[n][3] * SCALE2;
                cs[n][0] = x0; cs[n][1] = x1; cs[n][2] = x2; cs[n][3] = x3;
                mx0 = fmaxf(mx0, fmaxf(x0, x1));
                mx1 = fmaxf(mx1, fmaxf(x2, x3));
            }
        }
        mx0 = fmaxf(mx0, __shfl_xor_sync(0xffffffffu, mx0, 1));
        mx0 = fmaxf(mx0, __shfl_xor_sync(0xffffffffu, mx0, 2));
        mx1 = fmaxf(mx1, __shfl_xor_sync(0xffffffffu, mx1, 1));
        mx1 = fmaxf(mx1, __shfl_xor_sync(0xffffffffu, mx1, 2));
        float mn0 = fmaxf(mr0, mx0), mn1 = fmaxf(mr1, mx1);
        float al0 = ex2(mr0 - mn0), al1 = ex2(mr1 - mn1);
        mr0 = mn0; mr1 = mn1;

        // rescale running O only if any lane actually needs it (alpha != 1)
        if (__any_sync(0xffffffffu, (al0 != 1.f) | (al1 != 1.f))) {
            #pragma unroll
            for (int n = 0; n < 16; n++) {
                o[n][0] *= al0; o[n][1] *= al0;
                o[n][2] *= al1; o[n][3] *= al1;
            }
        }

        // ---- PV, exp fused per k-group; ph sweep then pl sweep ----
        float s0 = 0.f, s1 = 0.f;
        #pragma unroll
        for (int g = 0; g < 4; g++) {
            float p00 = ex2(cs[2*g][0]   - mn0), p01 = ex2(cs[2*g][1]   - mn0);
            float p02 = ex2(cs[2*g][2]   - mn1), p03 = ex2(cs[2*g][3]   - mn1);
            float p10 = ex2(cs[2*g+1][0] - mn0), p11 = ex2(cs[2*g+1][1] - mn0);
            float p12 = ex2(cs[2*g+1][2] - mn1), p13 = ex2(cs[2*g+1][3] - mn1);
            s0 += p00 + p01 + p10 + p11;
            s1 += p02 + p03 + p12 + p13;
            uint32_t ph[4], pl[4];
            split2h(p00, p01, ph[0], pl[0]);
            split2h(p02, p03, ph[1], pl[1]);
            split2h(p10, p11, ph[2], pl[2]);
            split2h(p12, p13, ph[3], pl[3]);
            // sweep 1: ph x all np (16 independent o accumulators)
            #pragma unroll
            for (int np = 0; np < 8; np++) {
                uint32_t bh[4];
                ldsm_x4t(bh, bufA + VHo + (uint32_t)((g * 16 + vRow) * 256) + (uint32_t)((np * 32 + vCol) ^ vXor));
                mma16816(o[2*np],   ph, bh);
                mma16816(o[2*np+1], ph, bh + 2);
            }
            // sweep 2: pl x all np
            #pragma unroll
            for (int np = 0; np < 8; np++) {
                uint32_t bh[4];
                ldsm_x4t(bh, bufA + VHo + (uint32_t)((g * 16 + vRow) * 256) + (uint32_t)((np * 32 + vCol) ^ vXor));
                mma16816(o[2*np],   pl, bh);
                mma16816(o[2*np+1], pl, bh + 2);
            }
        }
        s0 += __shfl_xor_sync(0xffffffffu, s0, 1);
        s0 += __shfl_xor_sync(0xffffffffu, s0, 2);
        s1 += __shfl_xor_sync(0xffffffffu, s1, 1);
        s1 += __shfl_xor_sync(0xffffffffu, s1, 2);
        l0r = l0r * al0 + s0;
        l1r = l1r * al1 + s1;
    }

    // ---- epilogue ----
    const float inv0 = 1.f / l0r, inv1 = 1.f / l1r;
    #pragma unroll
    for (int n = 0; n < 16; n++) {
        int col = n * 8 + cb;
        *(float2*)(Og + (size_t)r0gl * DDIM + col) = make_float2(o[n][0] * inv0, o[n][1] * inv0);
        *(float2*)(Og + (size_t)r1gl * DDIM + col) = make_float2(o[n][2] * inv1, o[n][3] * inv1);
    }
}

extern "C" void kernel_launch(void* const* d_in, const int* in_sizes, int n_in,
                              void* d_out, int out_size) {
    const float* Q = (const float*)d_in[0];
    const float* K = (const float*)d_in[1];
    const float* V = (const float*)d_in[2];
    float*       O = (float*)d_out;
    int B = in_sizes[0] / (S_LEN * DDIM);
    cudaFuncSetAttribute(attn_hmma, cudaFuncAttributeMaxDynamicSharedMemorySize, SMEM_BYTES);
    dim3 grid(S_LEN / BM, B);
    attn_hmma<<<grid, NT, SMEM_BYTES>>>(Q, K, V, O);
}

// round 11
// speedup vs baseline: 1.6969x; 1.0339x over previous
#include <cuda_runtime.h>
#include <cuda_fp16.h>
#include <stdint.h>
#include <math.h>

#define S_LEN 2048
#define DDIM  128
#define BM 64
#define BN 64
#define NT 128

// smem (96KB/CTA, 2 CTAs/SM): two 32KB fp16 buffers (KH|VH) + one 32KB raw fp32 stage
#define KHo 0
#define VHo 16384
#define BUF(s) ((s) * 32768)
#define ST 65536
#define SMEM_BYTES 98304
// prologue Q scratch overlays buf0
#define QH_S 0
#define QL_S 16384

static __device__ __forceinline__ uint32_t smem_u32(const void* p) {
    uint32_t a;
    asm("{ .reg .u64 t; cvta.to.shared.u64 t, %1; cvt.u32.u64 %0, t; }" : "=r"(a) : "l"(p));
    return a;
}
static __device__ __forceinline__ void ldsm_x4(uint32_t r[4], uint32_t a) {
    asm volatile("ldmatrix.sync.aligned.m8n8.x4.shared.b16 {%0,%1,%2,%3}, [%4];"
                 : "=r"(r[0]), "=r"(r[1]), "=r"(r[2]), "=r"(r[3]) : "r"(a));
}
static __device__ __forceinline__ void ldsm_x4t(uint32_t r[4], uint32_t a) {
    asm volatile("ldmatrix.sync.aligned.m8n8.x4.trans.shared.b16 {%0,%1,%2,%3}, [%4];"
                 : "=r"(r[0]), "=r"(r[1]), "=r"(r[2]), "=r"(r[3]) : "r"(a));
}
static __device__ __forceinline__ void mma16816(float c[4], const uint32_t a[4], const uint32_t b[2]) {
    asm volatile("mma.sync.aligned.m16n8k16.row.col.f32.f16.f16.f32 "
                 "{%0,%1,%2,%3}, {%4,%5,%6,%7}, {%8,%9}, {%0,%1,%2,%3};"
                 : "+f"(c[0]), "+f"(c[1]), "+f"(c[2]), "+f"(c[3])
                 : "r"(a[0]), "r"(a[1]), "r"(a[2]), "r"(a[3]), "r"(b[0]), "r"(b[1]));
}
static __device__ __forceinline__ void cp16(uint32_t dst, const void* src) {
    asm volatile("cp.async.cg.shared.global [%0], [%1], 16;" :: "r"(dst), "l"(src));
}
static __device__ __forceinline__ void cp_commit() {
    asm volatile("cp.async.commit_group;" ::: "memory");
}
static __device__ __forceinline__ void cp_wait0() {
    asm volatile("cp.async.wait_group 0;" ::: "memory");
}
static __device__ __forceinline__ float ex2(float x) {
    float y;
    asm("ex2.approx.f32 %0, %1;" : "=f"(y) : "f"(x));
    return y;
}
static __device__ __forceinline__ uint32_t packh2(float x, float y) {
    __half2 h = __floats2half2_rn(x, y);
    return *reinterpret_cast<uint32_t*>(&h);
}
static __device__ __forceinline__ void split2h(float x, float y, uint32_t& h, uint32_t& l) {
    __half hx = __float2half_rn(x), hy = __float2half_rn(y);
    h = ((uint32_t)__half_as_ushort(hy) << 16) | __half_as_ushort(hx);
    __half lx = __float2half_rn(x - __half2float(hx));
    __half ly = __float2half_rn(y - __half2float(hy));
    l = ((uint32_t)__half_as_ushort(ly) << 16) | __half_as_ushort(lx);
}

// convert one 128-thread chunk of the staged fp32 tile into an fp16 tile slot
#define CONV(c, dstc) { int i_ = tid + (c) * NT; int row_ = i_ >> 5, k4_ = i_ & 31;            \
    uint32_t off_ = (uint32_t)(row_ * 256 + ((k4_ * 8) ^ ((row_ & 7) << 4)));                  \
    float4 f_ = *(const float4*)(sm + ST + (size_t)i_ * 16);                                   \
    *(uint2*)((dstc) + off_) = make_uint2(packh2(f_.x, f_.y), packh2(f_.z, f_.w)); }
#define STAGE(gptr) { _Pragma("unroll")                                                        \
    for (int j_ = 0; j_ < 16; j_++) { int i_ = tid + j_ * NT;                                  \
        cp16(sb + ST + i_ * 16, (const void*)((gptr) + (size_t)i_ * 4)); } }

__global__ __launch_bounds__(NT, 2)
void attn_hmma(const float* __restrict__ Q, const float* __restrict__ K,
               const float* __restrict__ V, float* __restrict__ O) {
    extern __shared__ char sm[];
    const uint32_t sb = smem_u32(sm);
    const int tid  = threadIdx.x;
    const int lane = tid & 31;
    const int w    = tid >> 5;
    const int qt    = gridDim.x - 1 - blockIdx.x;   // heavy CTAs first
    const int b     = blockIdx.y;
    const int qbase = qt * BM;
    const int ntile = qt + 1;
    const int m0    = w * 16;

    const float* Qg = Q + (size_t)b * S_LEN * DDIM;
    const float* Kg = K + (size_t)b * S_LEN * DDIM;
    const float* Vg = V + (size_t)b * S_LEN * DDIM;
    float*       Og = O + (size_t)b * S_LEN * DDIM;

    // lane decodes
    const int aR   = m0 + (lane & 15);
    const int aK   = (lane & 16) ? 16 : 0;
    const int aXor = (aR & 7) << 4;
    const int kRow = (lane & 7) + ((lane & 16) ? 8 : 0);   // K x4: 2 n-tiles
    const int kCol = (lane & 8) ? 16 : 0;
    const int kXor = (lane & 7) << 4;
    const int vRow = (lane & 7) + ((lane & 8) ? 8 : 0);    // V x4t: 2 n-tiles
    const int vCol = (lane & 16) ? 16 : 0;
    const int vXor = (lane & 7) << 4;

    // ---- prologue: stage K0; Q -> fp16 scratch -> frags; convert K0,V0; stage K1 ----
    STAGE(Kg);
    cp_commit();
    #pragma unroll
    for (int j = 0; j < 16; j++) {
        int i = tid + j * NT;
        int row = i >> 5, k4 = i & 31;
        float4 q = ((const float4*)Qg)[(size_t)(qbase + row) * 32 + k4];
        uint32_t h0, l0, h1, l1;
        split2h(q.x, q.y, h0, l0); split2h(q.z, q.w, h1, l1);
        uint32_t off = (uint32_t)(row * 256 + ((k4 * 8) ^ ((row & 7) << 4)));
        *(uint2*)(sm + QH_S + off) = make_uint2(h0, h1);
        *(uint2*)(sm + QL_S + off) = make_uint2(l0, l1);
    }
    __syncthreads();
    uint32_t qh[8][4], ql[8][4];
    #pragma unroll
    for (int kk = 0; kk < 8; kk++) {
        ldsm_x4(qh[kk], sb + QH_S + aR * 256 + ((kk * 32 + aK) ^ aXor));
        ldsm_x4(ql[kk], sb + QL_S + aR * 256 + ((kk * 32 + aK) ^ aXor));
    }
    cp_wait0();
    __syncthreads();   // Q scratch reads done; buf0 may be overwritten
    #pragma unroll
    for (int c = 0; c < 16; c++) CONV(c, sm + BUF(0) + KHo);
    STAGE(Vg);
    cp_commit();
    cp_wait0();
    #pragma unroll
    for (int c = 0; c < 16; c++) CONV(c, sm + BUF(0) + VHo);
    if (ntile > 1) { STAGE(Kg + (size_t)BN * DDIM); cp_commit(); }
    __syncthreads();   // buf0 visible; invariant established

    float o[16][4];
    #pragma unroll
    for (int n = 0; n < 16; n++)
        #pragma unroll
        for (int i = 0; i < 4; i++) o[n][i] = 0.f;
    float mr0 = -INFINITY, mr1 = -INFINITY, l0r = 0.f, l1r = 0.f;

    const int r0gl = qbase + m0 + (lane >> 2);
    const int r1gl = r0gl + 8;
    const int cb   = (lane & 3) * 2;
    const float SCALE2 = 0.0883883476483184405f * 1.4426950408889634f;   // 1/sqrt(128)*log2(e)

    for (int t = 0; t < ntile; t++) {
        const int kb = t * BN;
        const bool more = (t + 1 < ntile);
        char* smB = sm + BUF((t + 1) & 1);
        const uint32_t bufA = sb + (uint32_t)BUF(t & 1);
        // invariant: bufA(K,V of tile t) ready+visible; ST holds K(t+1) committed (if more)

        if (more) cp_wait0();   // own K(t+1) chunks landed

        // ---- S = Q K^T; K(t+1) convert interleaved (2 chunks per kk) ----
        float cs[8][4];
        #pragma unroll
        for (int n = 0; n < 8; n++)
            #pragma unroll
            for (int i = 0; i < 4; i++) cs[n][i] = 0.f;

        #pragma unroll
        for (int kk = 0; kk < 8; kk++) {
            if (more) { CONV(2 * kk, smB + KHo); CONV(2 * kk + 1, smB + KHo); }
            #pragma unroll
            for (int np = 0; np < 4; np++) {
                uint32_t bh[4];
                ldsm_x4(bh, bufA + KHo + (uint32_t)((np * 16 + kRow) * 256) + (uint32_t)((kk * 32 + kCol) ^ kXor));
                mma16816(cs[2*np],   qh[kk], bh);
                mma16816(cs[2*np+1], qh[kk], bh + 2);
            }
            #pragma unroll
            for (int np = 0; np < 4; np++) {
                uint32_t bh[4];
                ldsm_x4(bh, bufA + KHo + (uint32_t)((np * 16 + kRow) * 256) + (uint32_t)((kk * 32 + kCol) ^ kXor));
                mma16816(cs[2*np],   ql[kk], bh);
                mma16816(cs[2*np+1], ql[kk], bh + 2);
            }
        }

        if (more) { STAGE(Vg + (size_t)(kb + BN) * DDIM); cp_commit(); }   // own ST chunks free (in-order)

        // ---- softmax (log2 domain) ----
        float mx0 = -INFINITY, mx1 = -INFINITY;
        if (kb + BN - 1 > qbase + m0) {
            #pragma unroll
            for (int n = 0; n < 8; n++) {
                int jg = kb + n * 8 + cb;
                float x0 = cs[n][0] * SCALE2; if (jg > r0gl)     x0 = -1e9f;
                float x1 = cs[n][1] * SCALE2; if (jg + 1 > r0gl) x1 = -1e9f;
                float x2 = cs[n][2] * SCALE2; if (jg > r1gl)     x2 = -1e9f;
                float x3 = cs[n][3] * SCALE2; if (jg + 1 > r1gl) x3 = -1e9f;
                cs[n][0] = x0; cs[n][1] = x1; cs[n][2] = x2; cs[n][3] = x3;
                mx0 = fmaxf(mx0, fmaxf(x0, x1));
                mx1 = fmaxf(mx1, fmaxf(x2, x3));
            }
        } else {
            #pragma unroll
            for (int n = 0; n < 8; n++) {
                float x0 = cs[n][0] * SCALE2, x1 = cs[n][1] * SCALE2;
                float x2 = cs[n][2] * SCALE2, x3 = cs[n][3] * SCALE2;
                cs[n][0] = x0; cs[n][1] = x1; cs[n][2] = x2; cs[n][3] = x3;
                mx0 = fmaxf(mx0, fmaxf(x0, x1));
                mx1 = fmaxf(mx1, fmaxf(x2, x3));
            }
        }
        mx0 = fmaxf(mx0, __shfl_xor_sync(0xffffffffu, mx0, 1));
        mx0 = fmaxf(mx0, __shfl_xor_sync(0xffffffffu, mx0, 2));
        mx1 = fmaxf(mx1, __shfl_xor_sync(0xffffffffu, mx1, 1));
        mx1 = fmaxf(mx1, __shfl_xor_sync(0xffffffffu, mx1, 2));
        float mn0 = fmaxf(mr0, mx0), mn1 = fmaxf(mr1, mx1);
        float al0 = ex2(mr0 - mn0), al1 = ex2(mr1 - mn1);
        mr0 = mn0; mr1 = mn1;

        if (__any_sync(0xffffffffu, (al0 != 1.f) | (al1 != 1.f))) {
            #pragma unroll
            for (int n = 0; n < 16; n++) {
                o[n][0] *= al0; o[n][1] *= al0;
                o[n][2] *= al1; o[n][3] *= al1;
            }
        }

        if (more) cp_wait0();   // own V(t+1) chunks landed

        // ---- PV; exp fused per k-group; V(t+1) convert interleaved (4 chunks per g) ----
        float s0 = 0.f, s1 = 0.f;
        #pragma unroll
        for (int g = 0; g < 4; g++) {
            if (more) {
                CONV(4 * g,     smB + VHo); CONV(4 * g + 1, smB + VHo);
                CONV(4 * g + 2, smB + VHo); CONV(4 * g + 3, smB + VHo);
            }
            float p00 = ex2(cs[2*g][0]   - mn0), p01 = ex2(cs[2*g][1]   - mn0);
            float p02 = ex2(cs[2*g][2]   - mn1), p03 = ex2(cs[2*g][3]   - mn1);
            float p10 = ex2(cs[2*g+1][0] - mn0), p11 = ex2(cs[2*g+1][1] - mn0);
            float p12 = ex2(cs[2*g+1][2] - mn1), p13 = ex2(cs[2*g+1][3] - mn1);
            s0 += p00 + p01 + p10 + p11;
            s1 += p02 + p03 + p12 + p13;
            uint32_t ph[4], pl[4];
            split2h(p00, p01, ph[0], pl[0]);
            split2h(p02, p03, ph[1], pl[1]);
            split2h(p10, p11, ph[2], pl[2]);
            split2h(p12, p13, ph[3], pl[3]);
            #pragma unroll
            for (int np = 0; np < 8; np++) {
                uint32_t bh[4];
                ldsm_x4t(bh, bufA + VHo + (uint32_t)((g * 16 + vRow) * 256) + (uint32_t)((np * 32 + vCol) ^ vXor));
                mma16816(o[2*np],   ph, bh);
                mma16816(o[2*np+1], ph, bh + 2);
            }
            #pragma unroll
            for (int np = 0; np < 8; np++) {
                uint32_t bh[4];
                ldsm_x4t(bh, bufA + VHo + (uint32_t)((g * 16 + vRow) * 256) + (uint32_t)((np * 32 + vCol) ^ vXor));
                mma16816(o[2*np],   pl, bh);
                mma16816(o[2*np+1], pl, bh + 2);
            }
        }
        s0 += __shfl_xor_sync(0xffffffffu, s0, 1);
        s0 += __shfl_xor_sync(0xffffffffu, s0, 2);
        s1 += __shfl_xor_sync(0xffffffffu, s1, 1);
        s1 += __shfl_xor_sync(0xffffffffu, s1, 2);
        l0r = l0r * al0 + s0;
        l1r = l1r * al1 + s1;

        if (t + 2 < ntile) { STAGE(Kg + (size_t)(kb + 2 * BN) * DDIM); cp_commit(); }
        __syncthreads();   // bufB (tile t+1) visible to all; bufA free for t+2 converts
    }

    // ---- epilogue ----
    const float inv0 = 1.f / l0r, inv1 = 1.f / l1r;
    #pragma unroll
    for (int n = 0; n < 16; n++) {
        int col = n * 8 + cb;
        *(float2*)(Og + (size_t)r0gl * DDIM + col) = make_float2(o[n][0] * inv0, o[n][1] * inv0);
        *(float2*)(Og + (size_t)r1gl * DDIM + col) = make_float2(o[n][2] * inv1, o[n][3] * inv1);
    }
}

extern "C" void kernel_launch(void* const* d_in, const int* in_sizes, int n_in,
                              void* d_out, int out_size) {
    const float* Q = (const float*)d_in[0];
    const float* K = (const float*)d_in[1];
    const float* V = (const float*)d_in[2];
    float*       O = (float*)d_out;
    int B = in_sizes[0] / (S_LEN * DDIM);
    cudaFuncSetAttribute(attn_hmma, cudaFuncAttributeMaxDynamicSharedMemorySize, SMEM_BYTES);
    dim3 grid(S_LEN / BM, B);
    attn_hmma<<<grid, NT, SMEM_BYTES>>>(Q, K, V, O);
}

// round 12
// speedup vs baseline: 2.1547x; 1.2698x over previous
#include <cuda_runtime.h>
#include <cuda_fp16.h>
#include <stdint.h>
#include <math.h>

#define S_LEN 2048
#define DDIM  128
#define BM 64
#define BN 64
#define NT 128

// smem (96KB/CTA): two 32KB fp16 buffers (KH|VH) + one 32KB raw fp32 stage
#define KHo 0
#define VHo 16384
#define BUF(s) ((s) * 32768)
#define ST 65536
#define SMEM_BYTES 98304
#define QH_S 0   // prologue Q scratch overlays buf0.K

static __device__ __forceinline__ uint32_t smem_u32(const void* p) {
    uint32_t a;
    asm("{ .reg .u64 t; cvta.to.shared.u64 t, %1; cvt.u32.u64 %0, t; }" : "=r"(a) : "l"(p));
    return a;
}
static __device__ __forceinline__ void ldsm_x4(uint32_t r[4], uint32_t a) {
    asm volatile("ldmatrix.sync.aligned.m8n8.x4.shared.b16 {%0,%1,%2,%3}, [%4];"
                 : "=r"(r[0]), "=r"(r[1]), "=r"(r[2]), "=r"(r[3]) : "r"(a));
}
static __device__ __forceinline__ void ldsm_x4t(uint32_t r[4], uint32_t a) {
    asm volatile("ldmatrix.sync.aligned.m8n8.x4.trans.shared.b16 {%0,%1,%2,%3}, [%4];"
                 : "=r"(r[0]), "=r"(r[1]), "=r"(r[2]), "=r"(r[3]) : "r"(a));
}
static __device__ __forceinline__ void mma16816(float c[4], const uint32_t a[4], const uint32_t b[2]) {
    asm volatile("mma.sync.aligned.m16n8k16.row.col.f32.f16.f16.f32 "
                 "{%0,%1,%2,%3}, {%4,%5,%6,%7}, {%8,%9}, {%0,%1,%2,%3};"
                 : "+f"(c[0]), "+f"(c[1]), "+f"(c[2]), "+f"(c[3])
                 : "r"(a[0]), "r"(a[1]), "r"(a[2]), "r"(a[3]), "r"(b[0]), "r"(b[1]));
}
static __device__ __forceinline__ void cp16(uint32_t dst, const void* src) {
    asm volatile("cp.async.cg.shared.global [%0], [%1], 16;" :: "r"(dst), "l"(src));
}
static __device__ __forceinline__ void cp_commit() {
    asm volatile("cp.async.commit_group;" ::: "memory");
}
static __device__ __forceinline__ void cp_wait0() {
    asm volatile("cp.async.wait_group 0;" ::: "memory");
}
static __device__ __forceinline__ float ex2(float x) {
    float y;
    asm("ex2.approx.f32 %0, %1;" : "=f"(y) : "f"(x));
    return y;
}
static __device__ __forceinline__ uint32_t packh2(float x, float y) {
    __half2 h = __floats2half2_rn(x, y);
    return *reinterpret_cast<uint32_t*>(&h);
}

#define CONV(c, dstc) { int i_ = tid + (c) * NT; int row_ = i_ >> 5, k4_ = i_ & 31;            \
    uint32_t off_ = (uint32_t)(row_ * 256 + ((k4_ * 8) ^ ((row_ & 7) << 4)));                  \
    float4 f_ = *(const float4*)(sm + ST + (size_t)i_ * 16);                                   \
    *(uint2*)((dstc) + off_) = make_uint2(packh2(f_.x, f_.y), packh2(f_.z, f_.w)); }
#define STAGE(gptr) { _Pragma("unroll")                                                        \
    for (int j_ = 0; j_ < 16; j_++) { int i_ = tid + j_ * NT;                                  \
        cp16(sb + ST + i_ * 16, (const void*)((gptr) + (size_t)i_ * 4)); } }

__global__ __launch_bounds__(NT, 2)
void attn_hmma(const float* __restrict__ Q, const float* __restrict__ K,
               const float* __restrict__ V, float* __restrict__ O) {
    extern __shared__ char sm[];
    const uint32_t sb = smem_u32(sm);
    const int tid  = threadIdx.x;
    const int lane = tid & 31;
    const int w    = tid >> 5;
    const int qt    = gridDim.x - 1 - blockIdx.x;   // heavy CTAs first
    const int b     = blockIdx.y;
    const int qbase = qt * BM;
    const int ntile = qt + 1;
    const int m0    = w * 16;

    const float* Qg = Q + (size_t)b * S_LEN * DDIM;
    const float* Kg = K + (size_t)b * S_LEN * DDIM;
    const float* Vg = V + (size_t)b * S_LEN * DDIM;
    float*       Og = O + (size_t)b * S_LEN * DDIM;

    // lane decodes
    const int aR   = m0 + (lane & 15);
    const int aK   = (lane & 16) ? 16 : 0;
    const int aXor = (aR & 7) << 4;
    const int kRow = (lane & 7) + ((lane & 16) ? 8 : 0);   // K x4: 2 n-tiles
    const int kCol = (lane & 8) ? 16 : 0;
    const int kXor = (lane & 7) << 4;
    const int vRow = (lane & 7) + ((lane & 8) ? 8 : 0);    // V x4t: 2 n-tiles
    const int vCol = (lane & 16) ? 16 : 0;
    const int vXor = (lane & 7) << 4;

    // ---- prologue: stage K0; Q -> fp16 scratch -> frags; convert K0,V0; stage K1 ----
    STAGE(Kg);
    cp_commit();
    #pragma unroll
    for (int j = 0; j < 8; j++) {
        int i = tid + j * NT;
        int row = i >> 4, k8 = i & 15;   // 8 fp32 per thread-chunk
        float4 qa = ((const float4*)Qg)[(size_t)(qbase + row) * 32 + k8 * 2];
        float4 qb = ((const float4*)Qg)[(size_t)(qbase + row) * 32 + k8 * 2 + 1];
        uint32_t off = (uint32_t)(row * 256 + ((k8 * 16) ^ ((row & 7) << 4)));
        *(uint4*)(sm + QH_S + off) = make_uint4(packh2(qa.x, qa.y), packh2(qa.z, qa.w),
                                                packh2(qb.x, qb.y), packh2(qb.z, qb.w));
    }
    __syncthreads();
    uint32_t qh[8][4];
    #pragma unroll
    for (int kk = 0; kk < 8; kk++)
        ldsm_x4(qh[kk], sb + QH_S + aR * 256 + ((kk * 32 + aK) ^ aXor));
    cp_wait0();
    __syncthreads();   // Q scratch reads done; buf0 may be overwritten
    #pragma unroll
    for (int c = 0; c < 16; c++) CONV(c, sm + BUF(0) + KHo);
    STAGE(Vg);
    cp_commit();
    cp_wait0();
    #pragma unroll
    for (int c = 0; c < 16; c++) CONV(c, sm + BUF(0) + VHo);
    if (ntile > 1) { STAGE(Kg + (size_t)BN * DDIM); cp_commit(); }
    __syncthreads();   // buf0 visible; loop invariant established

    float o[16][4];
    #pragma unroll
    for (int n = 0; n < 16; n++)
        #pragma unroll
        for (int i = 0; i < 4; i++) o[n][i] = 0.f;
    float mr0 = -INFINITY, mr1 = -INFINITY, l0r = 0.f, l1r = 0.f;

    const int r0gl = qbase + m0 + (lane >> 2);
    const int r1gl = r0gl + 8;
    const int cb   = (lane & 3) * 2;
    const float SCALE2 = 0.0883883476483184405f * 1.4426950408889634f;   // 1/sqrt(128)*log2(e)

    for (int t = 0; t < ntile; t++) {
        const int kb = t * BN;
        const bool more = (t + 1 < ntile);
        char* smB = sm + BUF((t + 1) & 1);
        const uint32_t bufA = sb + (uint32_t)BUF(t & 1);
        // invariant: bufA(K,V of tile t) ready+visible; ST holds K(t+1) committed (if more)

        if (more) cp_wait0();   // own K(t+1) chunks landed

        // ---- S = Q K^T (single fp16 pass); K(t+1) convert interleaved ----
        float cs[8][4];
        #pragma unroll
        for (int n = 0; n < 8; n++)
            #pragma unroll
            for (int i = 0; i < 4; i++) cs[n][i] = 0.f;

        #pragma unroll
        for (int kk = 0; kk < 8; kk++) {
            if (more) { CONV(2 * kk, smB + KHo); CONV(2 * kk + 1, smB + KHo); }
            #pragma unroll
            for (int np = 0; np < 4; np++) {
                uint32_t bh[4];
                ldsm_x4(bh, bufA + KHo + (uint32_t)((np * 16 + kRow) * 256) + (uint32_t)((kk * 32 + kCol) ^ kXor));
                mma16816(cs[2*np],   qh[kk], bh);
                mma16816(cs[2*np+1], qh[kk], bh + 2);
            }
        }

        if (more) { STAGE(Vg + (size_t)(kb + BN) * DDIM); cp_commit(); }

        // ---- softmax (log2 domain) ----
        float mx0 = -INFINITY, mx1 = -INFINITY;
        if (kb + BN - 1 > qbase + m0) {
            #pragma unroll
            for (int n = 0; n < 8; n++) {
                int jg = kb + n * 8 + cb;
                float x0 = cs[n][0] * SCALE2; if (jg > r0gl)     x0 = -1e9f;
                float x1 = cs[n][1] * SCALE2; if (jg + 1 > r0gl) x1 = -1e9f;
                float x2 = cs[n][2] * SCALE2; if (jg > r1gl)     x2 = -1e9f;
                float x3 = cs[n][3] * SCALE2; if (jg + 1 > r1gl) x3 = -1e9f;
                cs[n][0] = x0; cs[n][1] = x1; cs[n][2] = x2; cs[n][3] = x3;
                mx0 = fmaxf(mx0, fmaxf(x0, x1));
                mx1 = fmaxf(mx1, fmaxf(x2, x3));
            }
        } else {
            #pragma unroll
            for (int n = 0; n < 8; n++) {
                float x0 = cs[n][0] * SCALE2, x1 = cs[n][1] * SCALE2;
                float x2 = cs[n][2] * SCALE2, x3 = cs[n][3] * SCALE2;
                cs[n][0] = x0; cs[n][1] = x1; cs[n][2] = x2; cs[n][3] = x3;
                mx0 = fmaxf(mx0, fmaxf(x0, x1));
                mx1 = fmaxf(mx1, fmaxf(x2, x3));
            }
        }
        mx0 = fmaxf(mx0, __shfl_xor_sync(0xffffffffu, mx0, 1));
        mx0 = fmaxf(mx0, __shfl_xor_sync(0xffffffffu, mx0, 2));
        mx1 = fmaxf(mx1, __shfl_xor_sync(0xffffffffu, mx1, 1));
        mx1 = fmaxf(mx1, __shfl_xor_sync(0xffffffffu, mx1, 2));
        float mn0 = fmaxf(mr0, mx0), mn1 = fmaxf(mr1, mx1);
        float al0 = ex2(mr0 - mn0), al1 = ex2(mr1 - mn1);
        mr0 = mn0; mr1 = mn1;

        if (__any_sync(0xffffffffu, (al0 != 1.f) | (al1 != 1.f))) {
            #pragma unroll
            for (int n = 0; n < 16; n++) {
                o[n][0] *= al0; o[n][1] *= al0;
                o[n][2] *= al1; o[n][3] *= al1;
            }
        }

        if (more) cp_wait0();   // own V(t+1) chunks landed

        // ---- PV (single fp16 pass); exp fused; V(t+1) convert interleaved ----
        float s0 = 0.f, s1 = 0.f;
        #pragma unroll
        for (int g = 0; g < 4; g++) {
            if (more) {
                CONV(4 * g,     smB + VHo); CONV(4 * g + 1, smB + VHo);
                CONV(4 * g + 2, smB + VHo); CONV(4 * g + 3, smB + VHo);
            }
            float p00 = ex2(cs[2*g][0]   - mn0), p01 = ex2(cs[2*g][1]   - mn0);
            float p02 = ex2(cs[2*g][2]   - mn1), p03 = ex2(cs[2*g][3]   - mn1);
            float p10 = ex2(cs[2*g+1][0] - mn0), p11 = ex2(cs[2*g+1][1] - mn0);
            float p12 = ex2(cs[2*g+1][2] - mn1), p13 = ex2(cs[2*g+1][3] - mn1);
            s0 += p00 + p01 + p10 + p11;
            s1 += p02 + p03 + p12 + p13;
            uint32_t ph[4];
            ph[0] = packh2(p00, p01);
            ph[1] = packh2(p02, p03);
            ph[2] = packh2(p10, p11);
            ph[3] = packh2(p12, p13);
            #pragma unroll
            for (int np = 0; np < 8; np++) {
                uint32_t bh[4];
                ldsm_x4t(bh, bufA + VHo + (uint32_t)((g * 16 + vRow) * 256) + (uint32_t)((np * 32 + vCol) ^ vXor));
                mma16816(o[2*np],   ph, bh);
                mma16816(o[2*np+1], ph, bh + 2);
            }
        }
        s0 += __shfl_xor_sync(0xffffffffu, s0, 1);
        s0 += __shfl_xor_sync(0xffffffffu, s0, 2);
        s1 += __shfl_xor_sync(0xffffffffu, s1, 1);
        s1 += __shfl_xor_sync(0xffffffffu, s1, 2);
        l0r = l0r * al0 + s0;
        l1r = l1r * al1 + s1;

        if (t + 2 < ntile) { STAGE(Kg + (size_t)(kb + 2 * BN) * DDIM); cp_commit(); }
        __syncthreads();   // bufB visible to all; bufA free for t+2 converts
    }

    // ---- epilogue ----
    const float inv0 = 1.f / l0r, inv1 = 1.f / l1r;
    #pragma unroll
    for (int n = 0; n < 16; n++) {
        int col = n * 8 + cb;
        *(float2*)(Og + (size_t)r0gl * DDIM + col) = make_float2(o[n][0] * inv0, o[n][1] * inv0);
        *(float2*)(Og + (size_t)r1gl * DDIM + col) = make_float2(o[n][2] * inv1, o[n][3] * inv1);
    }
}

extern "C" void kernel_launch(void* const* d_in, const int* in_sizes, int n_in,
                              void* d_out, int out_size) {
    const float* Q = (const float*)d_in[0];
    const float* K = (const float*)d_in[1];
    const float* V = (const float*)d_in[2];
    float*       O = (float*)d_out;
    int B = in_sizes[0] / (S_LEN * DDIM);
    cudaFuncSetAttribute(attn_hmma, cudaFuncAttributeMaxDynamicSharedMemorySize, SMEM_BYTES);
    dim3 grid(S_LEN / BM, B);
    attn_hmma<<<grid, NT, SMEM_BYTES>>>(Q, K, V, O);
}

// round 13
// speedup vs baseline: 2.2313x; 1.0355x over previous
#include <cuda_runtime.h>
#include <cuda_fp16.h>
#include <stdint.h>
#include <math.h>

#define S_LEN 2048
#define DDIM  128
#define BM 64
#define BN 64
#define NT 128

// smem (96KB/CTA): two 32KB fp16 buffers (KH|VH) + one 32KB raw fp32 stage
#define KHo 0
#define VHo 16384
#define BUF(s) ((s) * 32768)
#define ST 65536
#define SMEM_BYTES 98304
#define QH_S 0   // prologue Q scratch overlays buf0.K

static __device__ __forceinline__ uint32_t smem_u32(const void* p) {
    uint32_t a;
    asm("{ .reg .u64 t; cvta.to.shared.u64 t, %1; cvt.u32.u64 %0, t; }" : "=r"(a) : "l"(p));
    return a;
}
static __device__ __forceinline__ void ldsm_x4(uint32_t r[4], uint32_t a) {
    asm volatile("ldmatrix.sync.aligned.m8n8.x4.shared.b16 {%0,%1,%2,%3}, [%4];"
                 : "=r"(r[0]), "=r"(r[1]), "=r"(r[2]), "=r"(r[3]) : "r"(a));
}
static __device__ __forceinline__ void ldsm_x4t(uint32_t r[4], uint32_t a) {
    asm volatile("ldmatrix.sync.aligned.m8n8.x4.trans.shared.b16 {%0,%1,%2,%3}, [%4];"
                 : "=r"(r[0]), "=r"(r[1]), "=r"(r[2]), "=r"(r[3]) : "r"(a));
}
static __device__ __forceinline__ void mma16816(float c[4], const uint32_t a[4], const uint32_t b[2]) {
    asm volatile("mma.sync.aligned.m16n8k16.row.col.f32.f16.f16.f32 "
                 "{%0,%1,%2,%3}, {%4,%5,%6,%7}, {%8,%9}, {%0,%1,%2,%3};"
                 : "+f"(c[0]), "+f"(c[1]), "+f"(c[2]), "+f"(c[3])
                 : "r"(a[0]), "r"(a[1]), "r"(a[2]), "r"(a[3]), "r"(b[0]), "r"(b[1]));
}
static __device__ __forceinline__ void cp16(uint32_t dst, const void* src) {
    asm volatile("cp.async.cg.shared.global [%0], [%1], 16;" :: "r"(dst), "l"(src));
}
static __device__ __forceinline__ void cp_commit() {
    asm volatile("cp.async.commit_group;" ::: "memory");
}
static __device__ __forceinline__ void cp_wait0() {
    asm volatile("cp.async.wait_group 0;" ::: "memory");
}
static __device__ __forceinline__ float ex2(float x) {
    float y;
    asm("ex2.approx.f32 %0, %1;" : "=f"(y) : "f"(x));
    return y;
}
static __device__ __forceinline__ uint32_t cvt_h2(float lo, float hi) {
    uint32_t r;
    asm("cvt.rn.f16x2.f32 %0, %1, %2;" : "=r"(r) : "f"(hi), "f"(lo));
    return r;
}
static __device__ __forceinline__ uint32_t ex2_h2(uint32_t h) {
    uint32_t r;
    asm("ex2.approx.f16x2 %0, %1;" : "=r"(r) : "r"(h));
    return r;
}
static __device__ __forceinline__ uint32_t packh2(float x, float y) {
    __half2 h = __floats2half2_rn(x, y);
    return *reinterpret_cast<uint32_t*>(&h);
}

#define CONV(c, dstc) { int i_ = tid + (c) * NT; int row_ = i_ >> 5, k4_ = i_ & 31;            \
    uint32_t off_ = (uint32_t)(row_ * 256 + ((k4_ * 8) ^ ((row_ & 7) << 4)));                  \
    float4 f_ = *(const float4*)(sm + ST + (size_t)i_ * 16);                                   \
    *(uint2*)((dstc) + off_) = make_uint2(packh2(f_.x, f_.y), packh2(f_.z, f_.w)); }
#define STAGE(gptr) { _Pragma("unroll")                                                        \
    for (int j_ = 0; j_ < 16; j_++) { int i_ = tid + j_ * NT;                                  \
        cp16(sb + ST + i_ * 16, (const void*)((gptr) + (size_t)i_ * 4)); } }

__global__ __launch_bounds__(NT, 2)
void attn_hmma(const float* __restrict__ Q, const float* __restrict__ K,
               const float* __restrict__ V, float* __restrict__ O) {
    extern __shared__ char sm[];
    const uint32_t sb = smem_u32(sm);
    const int tid  = threadIdx.x;
    const int lane = tid & 31;
    const int w    = tid >> 5;
    const int qt    = gridDim.x - 1 - blockIdx.x;   // heavy CTAs first
    const int b     = blockIdx.y;
    const int qbase = qt * BM;
    const int ntile = qt + 1;
    const int m0    = w * 16;

    const float* Qg = Q + (size_t)b * S_LEN * DDIM;
    const float* Kg = K + (size_t)b * S_LEN * DDIM;
    const float* Vg = V + (size_t)b * S_LEN * DDIM;
    float*       Og = O + (size_t)b * S_LEN * DDIM;

    // lane decodes
    const int aR   = m0 + (lane & 15);
    const int aK   = (lane & 16) ? 16 : 0;
    const int aXor = (aR & 7) << 4;
    const int kRow = (lane & 7) + ((lane & 16) ? 8 : 0);   // K x4: 2 n-tiles
    const int kCol = (lane & 8) ? 16 : 0;
    const int kXor = (lane & 7) << 4;
    const int vRow = (lane & 7) + ((lane & 8) ? 8 : 0);    // V x4t: 2 n-tiles
    const int vCol = (lane & 16) ? 16 : 0;
    const int vXor = (lane & 7) << 4;

    // B-fragment of all ones (fp16 1.0 = 0x3C00) for row-sum MMAs
    const uint32_t ones2[2] = {0x3C003C00u, 0x3C003C00u};
    // 1/sqrt(128) * log2(e): folded into Q so scores emerge in log2 domain
    const float QSCALE = 0.0883883476483184405f * 1.4426950408889634f;

    // ---- prologue: stage K0; Q (pre-scaled) -> fp16 scratch -> frags; convert K0,V0 ----
    STAGE(Kg);
    cp_commit();
    #pragma unroll
    for (int j = 0; j < 8; j++) {
        int i = tid + j * NT;
        int row = i >> 4, k8 = i & 15;
        float4 qa = ((const float4*)Qg)[(size_t)(qbase + row) * 32 + k8 * 2];
        float4 qb = ((const float4*)Qg)[(size_t)(qbase + row) * 32 + k8 * 2 + 1];
        uint32_t off = (uint32_t)(row * 256 + ((k8 * 16) ^ ((row & 7) << 4)));
        *(uint4*)(sm + QH_S + off) = make_uint4(
            packh2(qa.x * QSCALE, qa.y * QSCALE), packh2(qa.z * QSCALE, qa.w * QSCALE),
            packh2(qb.x * QSCALE, qb.y * QSCALE), packh2(qb.z * QSCALE, qb.w * QSCALE));
    }
    __syncthreads();
    uint32_t qh[8][4];
    #pragma unroll
    for (int kk = 0; kk < 8; kk++)
        ldsm_x4(qh[kk], sb + QH_S + aR * 256 + ((kk * 32 + aK) ^ aXor));
    cp_wait0();
    __syncthreads();   // Q scratch reads done; buf0 may be overwritten
    #pragma unroll
    for (int c = 0; c < 16; c++) CONV(c, sm + BUF(0) + KHo);
    STAGE(Vg);
    cp_commit();
    cp_wait0();
    #pragma unroll
    for (int c = 0; c < 16; c++) CONV(c, sm + BUF(0) + VHo);
    if (ntile > 1) { STAGE(Kg + (size_t)BN * DDIM); cp_commit(); }
    __syncthreads();   // buf0 visible; loop invariant established

    float o[16][4];
    #pragma unroll
    for (int n = 0; n < 16; n++)
        #pragma unroll
        for (int i = 0; i < 4; i++) o[n][i] = 0.f;
    float mr0 = -INFINITY, mr1 = -INFINITY, l0r = 0.f, l1r = 0.f;

    const int r0gl = qbase + m0 + (lane >> 2);
    const int r1gl = r0gl + 8;
    const int cb   = (lane & 3) * 2;

    for (int t = 0; t < ntile; t++) {
        const int kb = t * BN;
        const bool more = (t + 1 < ntile);
        char* smB = sm + BUF((t + 1) & 1);
        const uint32_t bufA = sb + (uint32_t)BUF(t & 1);
        // invariant: bufA(K,V of tile t) ready+visible; ST holds K(t+1) committed (if more)

        if (more) cp_wait0();   // own K(t+1) chunks landed

        // ---- S = Q K^T (fp16, scores in log2 domain); K(t+1) convert interleaved ----
        float cs[8][4];
        #pragma unroll
        for (int n = 0; n < 8; n++)
            #pragma unroll
            for (int i = 0; i < 4; i++) cs[n][i] = 0.f;

        #pragma unroll
        for (int kk = 0; kk < 8; kk++) {
            if (more) { CONV(2 * kk, smB + KHo); CONV(2 * kk + 1, smB + KHo); }
            #pragma unroll
            for (int np = 0; np < 4; np++) {
                uint32_t bh[4];
                ldsm_x4(bh, bufA + KHo + (uint32_t)((np * 16 + kRow) * 256) + (uint32_t)((kk * 32 + kCol) ^ kXor));
                mma16816(cs[2*np],   qh[kk], bh);
                mma16816(cs[2*np+1], qh[kk], bh + 2);
            }
        }

        if (more) { STAGE(Vg + (size_t)(kb + BN) * DDIM); cp_commit(); }

        // ---- softmax: mask (-inf) + row max; no scaling (folded into Q) ----
        float mx0 = -INFINITY, mx1 = -INFINITY;
        if (kb + BN - 1 > qbase + m0) {
            #pragma unroll
            for (int n = 0; n < 8; n++) {
                int jg = kb + n * 8 + cb;
                if (jg > r0gl)     cs[n][0] = -INFINITY;
                if (jg + 1 > r0gl) cs[n][1] = -INFINITY;
                if (jg > r1gl)     cs[n][2] = -INFINITY;
                if (jg + 1 > r1gl) cs[n][3] = -INFINITY;
                mx0 = fmaxf(mx0, fmaxf(cs[n][0], cs[n][1]));
                mx1 = fmaxf(mx1, fmaxf(cs[n][2], cs[n][3]));
            }
        } else {
            #pragma unroll
            for (int n = 0; n < 8; n++) {
                mx0 = fmaxf(mx0, fmaxf(cs[n][0], cs[n][1]));
                mx1 = fmaxf(mx1, fmaxf(cs[n][2], cs[n][3]));
            }
        }
        mx0 = fmaxf(mx0, __shfl_xor_sync(0xffffffffu, mx0, 1));
        mx0 = fmaxf(mx0, __shfl_xor_sync(0xffffffffu, mx0, 2));
        mx1 = fmaxf(mx1, __shfl_xor_sync(0xffffffffu, mx1, 1));
        mx1 = fmaxf(mx1, __shfl_xor_sync(0xffffffffu, mx1, 2));
        float mn0 = fmaxf(mr0, mx0), mn1 = fmaxf(mr1, mx1);
        float al0 = ex2(mr0 - mn0), al1 = ex2(mr1 - mn1);
        mr0 = mn0; mr1 = mn1;

        if (__any_sync(0xffffffffu, (al0 != 1.f) | (al1 != 1.f))) {
            #pragma unroll
            for (int n = 0; n < 16; n++) {
                o[n][0] *= al0; o[n][1] *= al0;
                o[n][2] *= al1; o[n][3] *= al1;
            }
        }

        if (more) cp_wait0();   // own V(t+1) chunks landed

        // ---- PV: exp directly in fp16x2 -> P frags; row-sum via ones-MMA ----
        float sacc[4] = {0.f, 0.f, 0.f, 0.f};
        #pragma unroll
        for (int g = 0; g < 4; g++) {
            if (more) {
                CONV(4 * g,     smB + VHo); CONV(4 * g + 1, smB + VHo);
                CONV(4 * g + 2, smB + VHo); CONV(4 * g + 3, smB + VHo);
            }
            uint32_t ph[4];
            ph[0] = ex2_h2(cvt_h2(cs[2*g][0]   - mn0, cs[2*g][1]   - mn0));
            ph[1] = ex2_h2(cvt_h2(cs[2*g][2]   - mn1, cs[2*g][3]   - mn1));
            ph[2] = ex2_h2(cvt_h2(cs[2*g+1][0] - mn0, cs[2*g+1][1] - mn0));
            ph[3] = ex2_h2(cvt_h2(cs[2*g+1][2] - mn1, cs[2*g+1][3] - mn1));
            mma16816(sacc, ph, ones2);   // row sums of P (tensor pipe is underused)
            #pragma unroll
            for (int np = 0; np < 8; np++) {
                uint32_t bh[4];
                ldsm_x4t(bh, bufA + VHo + (uint32_t)((g * 16 + vRow) * 256) + (uint32_t)((np * 32 + vCol) ^ vXor));
                mma16816(o[2*np],   ph, bh);
                mma16816(o[2*np+1], ph, bh + 2);
            }
        }
        l0r = l0r * al0 + sacc[0];
        l1r = l1r * al1 + sacc[2];

        if (t + 2 < ntile) { STAGE(Kg + (size_t)(kb + 2 * BN) * DDIM); cp_commit(); }
        __syncthreads();   // bufB visible to all; bufA free for t+2 converts
    }

    // ---- epilogue ----
    const float inv0 = 1.f / l0r, inv1 = 1.f / l1r;
    #pragma unroll
    for (int n = 0; n < 16; n++) {
        int col = n * 8 + cb;
        *(float2*)(Og + (size_t)r0gl * DDIM + col) = make_float2(o[n][0] * inv0, o[n][1] * inv0);
        *(float2*)(Og + (size_t)r1gl * DDIM + col) = make_float2(o[n][2] * inv1, o[n][3] * inv1);
    }
}

extern "C" void kernel_launch(void* const* d_in, const int* in_sizes, int n_in,
                              void* d_out, int out_size) {
    const float* Q = (const float*)d_in[0];
    const float* K = (const float*)d_in[1];
    const float* V = (const float*)d_in[2];
    float*       O = (float*)d_out;
    int B = in_sizes[0] / (S_LEN * DDIM);
    cudaFuncSetAttribute(attn_hmma, cudaFuncAttributeMaxDynamicSharedMemorySize, SMEM_BYTES);
    dim3 grid(S_LEN / BM, B);
    attn_hmma<<<grid, NT, SMEM_BYTES>>>(Q, K, V, O);
}